// round 4
// baseline (speedup 1.0000x reference)
#include <cuda_runtime.h>
#include <stdint.h>

// samx_qkv_1bit: suffix-automaton retrieval, 1024 independent serial rows.
// R4: explicit suffix-chain array -> key-side walks use INDEPENDENT batched
//     smem loads; record repacked {tr0:12,tr1:12,f:12,m:12,r+1:16} so the
//     r-propagation is a pure STS.16 per new-chain node (no loads), fused
//     into the chain-rebuild loop. Degrades to dependent walks if the chain
//     ever exceeds CAP (never for random data; correctness for any input).

#define BB 4
#define TT 2048
#define CC 256
#define NROWS (BB*CC)          // 1024
#define WPB (TT/32)            // 64 packed words per row
#define STATES 4096            // SAM has <= 2n-1 = 4095 states (ids 0..4094)
#define RPB 7                  // rows (warps) per block
#define CAP 64                 // chain-array capacity (per step chain grows by <=2)

typedef unsigned long long ull;
#define IDA 0xFFF              // 12-bit absent / -1 marker
#define F_SH 24
#define M_SH 36
#define R_SH 48

__device__ uint32_t g_qpack[NROWS*WPB];
__device__ uint32_t g_kpack[NROWS*WPB];
__device__ uint32_t g_vpack[NROWS*WPB];

// ---------------------------------------------------------------------------
// Pack kernel: binarize q,k,v into per-row bitstreams. Coalesced over c.
// ---------------------------------------------------------------------------
__global__ void samx_pack_kernel(const float* __restrict__ q,
                                 const float* __restrict__ k,
                                 const float* __restrict__ v) {
    int c  = threadIdx.x;
    int wi = blockIdx.x;
    int b  = blockIdx.y;
    int row = b * CC + c;
    size_t base = ((size_t)b * TT + (size_t)wi * 32) * CC + c;
    uint32_t qw = 0, kw = 0, vw = 0;
#pragma unroll
    for (int s = 0; s < 32; s++) {
        if (q[base + (size_t)s * CC] > 0.f) qw |= 1u << s;
        if (k[base + (size_t)s * CC] > 0.f) kw |= 1u << s;
        if (v[base + (size_t)s * CC] > 0.f) vw |= 1u << s;
    }
    g_qpack[row * WPB + wi] = qw;
    g_kpack[row * WPB + wi] = kw;
    g_vpack[row * WPB + wi] = vw;
}

// ---------------------------------------------------------------------------
// Main SAM kernel: one warp per row, lane 0 active. Records in smem.
// ---------------------------------------------------------------------------
extern "C" __global__ void __launch_bounds__(32*RPB, 1)
samx_sam_kernel(const float* __restrict__ e, float* __restrict__ out) {
    extern __shared__ ull smem[];
    int warp = threadIdx.x >> 5;
    int lane = threadIdx.x & 31;
    int row  = blockIdx.x * RPB + warp;

    ull* S = smem + (size_t)warp * STATES;
    unsigned short* Sr = (unsigned short*)S;              // r+1 halfword = idx 4n+3
    uint32_t* vpk_s = (uint32_t*)(smem + (size_t)RPB * STATES) + warp * WPB;

    if (row < NROWS) {
        vpk_s[lane]      = g_vpack[row * WPB + lane];
        vpk_s[lane + 32] = g_vpack[row * WPB + lane + 32];
    }
    __syncwarp();
    if (lane != 0 || row >= NROWS) return;

    const uint32_t* qpk = g_qpack + row * WPB;
    const uint32_t* kpk = g_kpack + row * WPB;

    int b = row >> 8;
    int c = row & (CC - 1);
    float ev = e[c];
    float* op = out + (size_t)b * TT * CC + c;

    // root: tr absent, f=-1, m=0
    S[0] = (ull)IDA | ((ull)IDA << 12) | ((ull)IDA << F_SH);

    // suffix-chain arrays (local, ping-pong). OC[0] == g always.
    unsigned short CHbuf[2][CAP];
    unsigned short* OC = CHbuf[0];
    unsigned short* NC = CHbuf[1];
    int L = 1; OC[0] = 0;
    bool degraded = false;

    int g = 0, u = 1, w = 0, h = 0;
    uint32_t qw = 0, kw = 0;

    for (int i = 0; i < TT; i++) {
        if ((i & 31) == 0) { int wi = i >> 5; qw = qpk[wi]; kw = kpk[wi]; }
        int qs = ((qw >> (i & 31)) & 1) ? 12 : 0;
        int ks = ((kw >> (i & 31)) & 1) ? 12 : 0;

        // ---- query: extend match with symbol q via suffix links ----
        int p = w, x = h;
        for (;;) {
            if (p < 0) { p = 0; x = 0; break; }
            ull rec = S[p];
            int tq = (int)((rec >> qs) & IDA);
            if (tq != IDA) { p = tq; x += 1; break; }
            int mp = (int)((rec >> M_SH) & IDA);
            if (x > mp) x = mp;
            int f = (int)((rec >> F_SH) & IDA);
            p = (f == IDA) ? -1 : f;
        }
        int y = 0;
        if (x > 0) {
            ull recv = S[p];
            for (;;) {
                int f = (int)((recv >> F_SH) & IDA);
                if (f == IDA) break;
                ull recf = S[f];
                if ((int)((recf >> M_SH) & IDA) >= x) recv = recf;
                else break;
            }
            int idx = (int)(recv >> R_SH);              // r+1
            y = (int)((vpk_s[idx >> 5] >> (idx & 31)) & 1u);
        }
        op[(size_t)i * CC] = y ? ev : -ev;
        w = p; h = x;

        // ---- key: SAM extension + chain rebuild + fused r-propagation ----
        int j = u++;
        int fj;
        unsigned short rv = (unsigned short)(i + 1);    // r+1 value for this step

        if (!degraded) {
            // Phase A: scan old chain for first node with existing tk.
            int s = 0;
            int o = g;                                   // OC[0] == g, no load
            ull rec;
            int d = -1;
            for (;;) {
                rec = S[o];
                int tk = (int)((rec >> ks) & IDA);
                if (tk != IDA) { d = tk; break; }
                S[o] = (rec & ~((ull)IDA << ks)) | ((ull)j << ks);
                s++;
                if (s >= L) break;
                o = OC[s];
            }

            int nidx;
            if (d < 0) {                                 // symbol k never seen
                fj = 0;
                NC[0] = (unsigned short)j; NC[1] = 0; nidx = 2;
            } else {
                ull recd = S[d];
                int md = (int)((recd >> M_SH) & IDA);
                int mp = (int)((rec  >> M_SH) & IDA);
                bool redir;
                if (mp + 1 == md) {
                    fj = d;
                    redir = false;
                } else {
                    int bc = u++;                        // clone of d with m=mp+1
                    S[bc] = (recd & ~((ull)IDA << M_SH)) | ((ull)(mp + 1) << M_SH);
                    S[d]  = (recd & ~((ull)IDA << F_SH)) | ((ull)bc << F_SH);
                    // redirect OC[s] itself
                    S[o]  = (rec & ~((ull)IDA << ks)) | ((ull)bc << ks);
                    fj = bc;
                    redir = true;
                }
                NC[0] = (unsigned short)j;
                NC[1] = (unsigned short)fj;
                Sr[(fj << 2) | 3] = rv;                  // propagate r to fj
                nidx = 2;
                int prev = fj;
                // Phase B/C: remaining old-chain nodes -> redirects + new chain
                // (addresses known upfront -> loads pipeline independently)
#pragma unroll 4
                for (int t = s + 1; t < L; t++) {
                    int ot = OC[t];
                    ull rt = S[ot];
                    int tgt = (int)((rt >> ks) & IDA);
                    if (redir) {
                        if (tgt == d) {
                            S[ot] = (rt & ~((ull)IDA << ks)) | ((ull)fj << ks);
                            continue;                    // dup of fj
                        }
                        redir = false;
                    }
                    if (tgt != prev) {
                        NC[nidx++] = (unsigned short)tgt;
                        Sr[(tgt << 2) | 3] = rv;         // fused r-propagation
                        prev = tgt;
                    }
                }
                NC[nidx++] = 0;                          // root terminal (r unused)
            }
            // swap chain buffers
            { unsigned short* tmp = OC; OC = NC; NC = tmp; }
            L = nidx;
            if (L > CAP - 2) degraded = true;            // writes this step were <= CAP
        } else {
            // ---- degraded fallback: dependent walks (always correct) ----
            int p2 = g;
            for (;;) {
                if (p2 < 0) { fj = 0; break; }
                ull t = S[p2];
                int tk = (int)((t >> ks) & IDA);
                if (tk == IDA) {
                    S[p2] = (t & ~((ull)IDA << ks)) | ((ull)j << ks);
                    int f = (int)((t >> F_SH) & IDA);
                    p2 = (f == IDA) ? -1 : f;
                } else {
                    int d = tk;
                    ull recd = S[d];
                    int md = (int)((recd >> M_SH) & IDA);
                    int mp = (int)((t >> M_SH) & IDA);
                    if (mp + 1 == md) {
                        fj = d;
                    } else {
                        int bc = u++;
                        S[bc] = (recd & ~((ull)IDA << M_SH)) | ((ull)(mp + 1) << M_SH);
                        S[d]  = (recd & ~((ull)IDA << F_SH)) | ((ull)bc << F_SH);
                        fj = bc;
                        for (;;) {
                            ull t2 = S[p2];
                            if (((t2 >> ks) & IDA) != (ull)d) break;
                            S[p2] = (t2 & ~((ull)IDA << ks)) | ((ull)bc << ks);
                            int f = (int)((t2 >> F_SH) & IDA);
                            if (f == IDA) break;
                            p2 = f;
                        }
                    }
                    break;
                }
            }
            // dependent r-propagation down fj's chain (j handled by its store)
            int vst = fj;
            while (vst != 0) {
                ull rc = S[vst];
                Sr[(vst << 2) | 3] = rv;
                int f = (int)((rc >> F_SH) & IDA);
                if (f == IDA) break;
                vst = f;
            }
        }

        // new state j: tr absent, f=fj, m=i+1, r+1=i+1
        S[j] = (ull)IDA | ((ull)IDA << 12)
             | ((ull)fj << F_SH)
             | ((ull)(i + 1) << M_SH)
             | ((ull)(i + 1) << R_SH);
        g = j;
    }
}

extern "C" void kernel_launch(void* const* d_in, const int* in_sizes, int n_in,
                              void* d_out, int out_size) {
    const float* q = (const float*)d_in[0];
    const float* k = (const float*)d_in[1];
    const float* v = (const float*)d_in[2];
    const float* e = (const float*)d_in[3];
    float* out = (float*)d_out;

    dim3 pg(WPB, BB);
    samx_pack_kernel<<<pg, CC>>>(q, k, v);

    size_t smem = (size_t)RPB * STATES * sizeof(ull)
                + (size_t)RPB * WPB * sizeof(uint32_t);   // 229376 + 1792 = 231168
    cudaFuncSetAttribute(samx_sam_kernel,
                         cudaFuncAttributeMaxDynamicSharedMemorySize, (int)smem);
    int blocks = (NROWS + RPB - 1) / RPB;                 // 147
    samx_sam_kernel<<<blocks, 32 * RPB, smem>>>(e, out);
}

// round 5
// speedup vs baseline: 1.1528x; 1.1528x over previous
#include <cuda_runtime.h>
#include <stdint.h>

// samx_qkv_1bit: suffix-automaton retrieval, 1024 independent serial rows.
// R5 = R4 algorithm (explicit suffix-chain array, store-only r-propagation)
//      with the chain ping-pong buffers in SHARED memory (R4 accidentally put
//      them in local memory -> LDL/STL through L2, regression).
// smem/block: 229376 (records) + 1792 (vpk) + 1120 (chains) = 232288 <= 232448.

#define BB 4
#define TT 2048
#define CC 256
#define NROWS (BB*CC)          // 1024
#define WPB (TT/32)            // 64 packed words per row
#define STATES 4096            // SAM has <= 2n-1 = 4095 states (ids 0..4094)
#define RPB 7                  // rows (warps) per block
#define CAP 40                 // chain capacity (random data needs ~25; fallback covers rest)

typedef unsigned long long ull;
#define IDA 0xFFF              // 12-bit absent / -1 marker
#define F_SH 24
#define M_SH 36
#define R_SH 48

__device__ uint32_t g_qpack[NROWS*WPB];
__device__ uint32_t g_kpack[NROWS*WPB];
__device__ uint32_t g_vpack[NROWS*WPB];

// ---------------------------------------------------------------------------
// Pack kernel: binarize q,k,v into per-row bitstreams. Coalesced over c.
// ---------------------------------------------------------------------------
__global__ void samx_pack_kernel(const float* __restrict__ q,
                                 const float* __restrict__ k,
                                 const float* __restrict__ v) {
    int c  = threadIdx.x;
    int wi = blockIdx.x;
    int b  = blockIdx.y;
    int row = b * CC + c;
    size_t base = ((size_t)b * TT + (size_t)wi * 32) * CC + c;
    uint32_t qw = 0, kw = 0, vw = 0;
#pragma unroll
    for (int s = 0; s < 32; s++) {
        if (q[base + (size_t)s * CC] > 0.f) qw |= 1u << s;
        if (k[base + (size_t)s * CC] > 0.f) kw |= 1u << s;
        if (v[base + (size_t)s * CC] > 0.f) vw |= 1u << s;
    }
    g_qpack[row * WPB + wi] = qw;
    g_kpack[row * WPB + wi] = kw;
    g_vpack[row * WPB + wi] = vw;
}

// ---------------------------------------------------------------------------
// Main SAM kernel: one warp per row, lane 0 active. Everything in smem.
// ---------------------------------------------------------------------------
extern "C" __global__ void __launch_bounds__(32*RPB, 1)
samx_sam_kernel(const float* __restrict__ e, float* __restrict__ out) {
    extern __shared__ ull smem[];
    int warp = threadIdx.x >> 5;
    int lane = threadIdx.x & 31;
    int row  = blockIdx.x * RPB + warp;

    ull* S = smem + (size_t)warp * STATES;
    unsigned short* Sr = (unsigned short*)S;              // r+1 halfword = idx 4n+3
    uint32_t* vpk_s = (uint32_t*)(smem + (size_t)RPB * STATES) + warp * WPB;
    unsigned short* CH = (unsigned short*)((char*)smem
                        + (size_t)RPB * STATES * sizeof(ull)
                        + (size_t)RPB * WPB * sizeof(uint32_t))
                        + warp * 2 * CAP;

    if (row < NROWS) {
        vpk_s[lane]      = g_vpack[row * WPB + lane];
        vpk_s[lane + 32] = g_vpack[row * WPB + lane + 32];
    }
    __syncwarp();
    if (lane != 0 || row >= NROWS) return;

    const uint32_t* qpk = g_qpack + row * WPB;
    const uint32_t* kpk = g_kpack + row * WPB;

    int b = row >> 8;
    int c = row & (CC - 1);
    float ev = e[c];
    float* op = out + (size_t)b * TT * CC + c;

    // root: tr absent, f=-1, m=0
    S[0] = (ull)IDA | ((ull)IDA << 12) | ((ull)IDA << F_SH);

    // suffix-chain ping-pong (smem). OC[0] == g always.
    unsigned short* OC = CH;
    unsigned short* NC = CH + CAP;
    int L = 1; OC[0] = 0;
    bool degraded = false;

    int g = 0, u = 1, w = 0, h = 0;
    uint32_t qw = 0, kw = 0;

    for (int i = 0; i < TT; i++) {
        if ((i & 31) == 0) { int wi = i >> 5; qw = qpk[wi]; kw = kpk[wi]; }
        int qs = ((qw >> (i & 31)) & 1) ? 12 : 0;
        int ks = ((kw >> (i & 31)) & 1) ? 12 : 0;

        // ---- query: extend match with symbol q via suffix links ----
        int p = w, x = h;
        for (;;) {
            if (p < 0) { p = 0; x = 0; break; }
            ull rec = S[p];
            int tq = (int)((rec >> qs) & IDA);
            if (tq != IDA) { p = tq; x += 1; break; }
            int mp = (int)((rec >> M_SH) & IDA);
            if (x > mp) x = mp;
            int f = (int)((rec >> F_SH) & IDA);
            p = (f == IDA) ? -1 : f;
        }
        int y = 0;
        if (x > 0) {
            ull recv = S[p];
            for (;;) {
                int f = (int)((recv >> F_SH) & IDA);
                if (f == IDA) break;
                ull recf = S[f];
                if ((int)((recf >> M_SH) & IDA) >= x) recv = recf;
                else break;
            }
            int idx = (int)(recv >> R_SH);              // r+1
            y = (int)((vpk_s[idx >> 5] >> (idx & 31)) & 1u);
        }
        op[(size_t)i * CC] = y ? ev : -ev;
        w = p; h = x;

        // ---- key: SAM extension + chain rebuild + fused r-propagation ----
        int j = u++;
        int fj;
        unsigned short rv = (unsigned short)(i + 1);    // r+1 value for this step

        if (!degraded) {
            // Phase A: scan old chain for first node with existing tk.
            int s = 0;
            int o = g;                                   // OC[0] == g, no load
            ull rec;
            int d = -1;
            for (;;) {
                rec = S[o];
                int tk = (int)((rec >> ks) & IDA);
                if (tk != IDA) { d = tk; break; }
                S[o] = (rec & ~((ull)IDA << ks)) | ((ull)j << ks);
                s++;
                if (s >= L) break;
                o = OC[s];
            }

            int nidx;
            if (d < 0) {                                 // symbol k never seen
                fj = 0;
                NC[0] = (unsigned short)j; NC[1] = 0; nidx = 2;
            } else {
                ull recd = S[d];
                int md = (int)((recd >> M_SH) & IDA);
                int mp = (int)((rec  >> M_SH) & IDA);
                bool redir;
                if (mp + 1 == md) {
                    fj = d;
                    redir = false;
                } else {
                    int bc = u++;                        // clone of d with m=mp+1
                    S[bc] = (recd & ~((ull)IDA << M_SH)) | ((ull)(mp + 1) << M_SH);
                    S[d]  = (recd & ~((ull)IDA << F_SH)) | ((ull)bc << F_SH);
                    // redirect OC[s] itself
                    S[o]  = (rec & ~((ull)IDA << ks)) | ((ull)bc << ks);
                    fj = bc;
                    redir = true;
                }
                NC[0] = (unsigned short)j;
                NC[1] = (unsigned short)fj;
                Sr[(fj << 2) | 3] = rv;                  // propagate r to fj
                nidx = 2;
                int prev = fj;
                // Phase B/C: remaining old-chain nodes -> redirects + new chain
#pragma unroll 4
                for (int t = s + 1; t < L; t++) {
                    int ot = OC[t];
                    ull rt = S[ot];
                    int tgt = (int)((rt >> ks) & IDA);
                    if (redir) {
                        if (tgt == d) {
                            S[ot] = (rt & ~((ull)IDA << ks)) | ((ull)fj << ks);
                            continue;                    // dup of fj
                        }
                        redir = false;
                    }
                    if (tgt != prev) {
                        NC[nidx++] = (unsigned short)tgt;
                        Sr[(tgt << 2) | 3] = rv;         // fused r-propagation
                        prev = tgt;
                    }
                }
                NC[nidx++] = 0;                          // root terminal (r unused)
            }
            // swap chain buffers
            { unsigned short* tmp = OC; OC = NC; NC = tmp; }
            L = nidx;
            if (L > CAP - 2) degraded = true;            // this step wrote <= CAP
        } else {
            // ---- degraded fallback: dependent walks (always correct) ----
            int p2 = g;
            for (;;) {
                if (p2 < 0) { fj = 0; break; }
                ull t = S[p2];
                int tk = (int)((t >> ks) & IDA);
                if (tk == IDA) {
                    S[p2] = (t & ~((ull)IDA << ks)) | ((ull)j << ks);
                    int f = (int)((t >> F_SH) & IDA);
                    p2 = (f == IDA) ? -1 : f;
                } else {
                    int d = tk;
                    ull recd = S[d];
                    int md = (int)((recd >> M_SH) & IDA);
                    int mp = (int)((t >> M_SH) & IDA);
                    if (mp + 1 == md) {
                        fj = d;
                    } else {
                        int bc = u++;
                        S[bc] = (recd & ~((ull)IDA << M_SH)) | ((ull)(mp + 1) << M_SH);
                        S[d]  = (recd & ~((ull)IDA << F_SH)) | ((ull)bc << F_SH);
                        fj = bc;
                        for (;;) {
                            ull t2 = S[p2];
                            if (((t2 >> ks) & IDA) != (ull)d) break;
                            S[p2] = (t2 & ~((ull)IDA << ks)) | ((ull)bc << ks);
                            int f = (int)((t2 >> F_SH) & IDA);
                            if (f == IDA) break;
                            p2 = f;
                        }
                    }
                    break;
                }
            }
            int vst = fj;
            while (vst != 0) {
                ull rc = S[vst];
                Sr[(vst << 2) | 3] = rv;
                int f = (int)((rc >> F_SH) & IDA);
                if (f == IDA) break;
                vst = f;
            }
        }

        // new state j: tr absent, f=fj, m=i+1, r+1=i+1
        S[j] = (ull)IDA | ((ull)IDA << 12)
             | ((ull)fj << F_SH)
             | ((ull)(i + 1) << M_SH)
             | ((ull)(i + 1) << R_SH);
        g = j;
    }
}

extern "C" void kernel_launch(void* const* d_in, const int* in_sizes, int n_in,
                              void* d_out, int out_size) {
    const float* q = (const float*)d_in[0];
    const float* k = (const float*)d_in[1];
    const float* v = (const float*)d_in[2];
    const float* e = (const float*)d_in[3];
    float* out = (float*)d_out;

    dim3 pg(WPB, BB);
    samx_pack_kernel<<<pg, CC>>>(q, k, v);

    size_t smem = (size_t)RPB * STATES * sizeof(ull)
                + (size_t)RPB * WPB * sizeof(uint32_t)
                + (size_t)RPB * 2 * CAP * sizeof(unsigned short);  // 232288
    cudaFuncSetAttribute(samx_sam_kernel,
                         cudaFuncAttributeMaxDynamicSharedMemorySize, (int)smem);
    int blocks = (NROWS + RPB - 1) / RPB;                 // 147
    samx_sam_kernel<<<blocks, 32 * RPB, smem>>>(e, out);
}

// round 6
// speedup vs baseline: 1.3572x; 1.1773x over previous
#include <cuda_runtime.h>
#include <stdint.h>

// samx_qkv_1bit: suffix-automaton retrieval, 1024 independent serial rows.
// R6 = R5 (explicit suffix chain in smem, store-only r-propagation) with a
//      BRANCH-FREE chain-rebuild loop: clone redirects hoisted to a pre-loop,
//      dedup via predicated increment, r-stores unconditional (idempotent).
// smem/block: 229376 (records) + 1792 (vpk) + 1120 (chains) = 232288.

#define BB 4
#define TT 2048
#define CC 256
#define NROWS (BB*CC)          // 1024
#define WPB (TT/32)            // 64 packed words per row
#define STATES 4096            // SAM has <= 2n-1 = 4095 states
#define RPB 7                  // rows (warps) per block
#define CAP 40                 // chain capacity; fallback covers overflow

typedef unsigned long long ull;
#define IDA 0xFFF              // 12-bit absent / -1 marker
#define F_SH 24
#define M_SH 36
#define R_SH 48

__device__ uint32_t g_qpack[NROWS*WPB];
__device__ uint32_t g_kpack[NROWS*WPB];
__device__ uint32_t g_vpack[NROWS*WPB];

// ---------------------------------------------------------------------------
__global__ void samx_pack_kernel(const float* __restrict__ q,
                                 const float* __restrict__ k,
                                 const float* __restrict__ v) {
    int c  = threadIdx.x;
    int wi = blockIdx.x;
    int b  = blockIdx.y;
    int row = b * CC + c;
    size_t base = ((size_t)b * TT + (size_t)wi * 32) * CC + c;
    uint32_t qw = 0, kw = 0, vw = 0;
#pragma unroll
    for (int s = 0; s < 32; s++) {
        if (q[base + (size_t)s * CC] > 0.f) qw |= 1u << s;
        if (k[base + (size_t)s * CC] > 0.f) kw |= 1u << s;
        if (v[base + (size_t)s * CC] > 0.f) vw |= 1u << s;
    }
    g_qpack[row * WPB + wi] = qw;
    g_kpack[row * WPB + wi] = kw;
    g_vpack[row * WPB + wi] = vw;
}

// ---------------------------------------------------------------------------
extern "C" __global__ void __launch_bounds__(32*RPB, 1)
samx_sam_kernel(const float* __restrict__ e, float* __restrict__ out) {
    extern __shared__ ull smem[];
    int warp = threadIdx.x >> 5;
    int lane = threadIdx.x & 31;
    int row  = blockIdx.x * RPB + warp;

    ull* S = smem + (size_t)warp * STATES;
    unsigned short* Sr = (unsigned short*)S;              // r+1 halfword = idx 4n+3
    uint32_t* vpk_s = (uint32_t*)(smem + (size_t)RPB * STATES) + warp * WPB;
    unsigned short* CH = (unsigned short*)((char*)smem
                        + (size_t)RPB * STATES * sizeof(ull)
                        + (size_t)RPB * WPB * sizeof(uint32_t))
                        + warp * 2 * CAP;

    if (row < NROWS) {
        vpk_s[lane]      = g_vpack[row * WPB + lane];
        vpk_s[lane + 32] = g_vpack[row * WPB + lane + 32];
    }
    __syncwarp();
    if (lane != 0 || row >= NROWS) return;

    const uint32_t* qpk = g_qpack + row * WPB;
    const uint32_t* kpk = g_kpack + row * WPB;

    int b = row >> 8;
    int c = row & (CC - 1);
    float ev = e[c];
    float* op = out + (size_t)b * TT * CC + c;

    // root: tr absent, f=-1, m=0
    S[0] = (ull)IDA | ((ull)IDA << 12) | ((ull)IDA << F_SH);

    unsigned short* OC = CH;
    unsigned short* NC = CH + CAP;
    int L = 1; OC[0] = 0;
    bool degraded = false;

    int g = 0, u = 1, w = 0, h = 0;
    uint32_t qw = 0, kw = 0;

    for (int i = 0; i < TT; i++) {
        if ((i & 31) == 0) { int wi = i >> 5; qw = qpk[wi]; kw = kpk[wi]; }
        int qs = ((qw >> (i & 31)) & 1) ? 12 : 0;
        int ks = ((kw >> (i & 31)) & 1) ? 12 : 0;

        // ---- query: extend match with symbol q via suffix links ----
        int p = w, x = h;
        for (;;) {
            if (p < 0) { p = 0; x = 0; break; }
            ull rec = S[p];
            int tq = (int)((rec >> qs) & IDA);
            if (tq != IDA) { p = tq; x += 1; break; }
            int mp = (int)((rec >> M_SH) & IDA);
            if (x > mp) x = mp;
            int f = (int)((rec >> F_SH) & IDA);
            p = (f == IDA) ? -1 : f;
        }
        int y = 0;
        if (x > 0) {
            ull recv = S[p];
            for (;;) {
                int f = (int)((recv >> F_SH) & IDA);
                if (f == IDA) break;
                ull recf = S[f];
                if ((int)((recf >> M_SH) & IDA) >= x) recv = recf;
                else break;
            }
            int idx = (int)(recv >> R_SH);              // r+1
            y = (int)((vpk_s[idx >> 5] >> (idx & 31)) & 1u);
        }
        op[(size_t)i * CC] = y ? ev : -ev;
        w = p; h = x;

        // ---- key: SAM extension + chain rebuild + fused r-propagation ----
        int j = u++;
        int fj;
        unsigned short rv = (unsigned short)(i + 1);

        if (!degraded) {
            // Phase A: walk old chain while tk absent, planting tk=j.
            int s = 0;
            int o = g;                                   // OC[0] == g
            ull rec = S[o];
            int d = -1;
            for (;;) {
                int tk = (int)((rec >> ks) & IDA);
                if (tk != IDA) { d = tk; break; }
                S[o] = (rec & ~((ull)IDA << ks)) | ((ull)j << ks);
                s++;
                if (s >= L) break;
                o = OC[s];
                rec = S[o];
            }

            int nidx;
            if (d < 0) {                                 // symbol never seen
                fj = 0;
                NC[0] = (unsigned short)j; NC[1] = 0; nidx = 2;
            } else {
                ull recd = S[d];
                int md = (int)((recd >> M_SH) & IDA);
                int mp = (int)((rec  >> M_SH) & IDA);
                int t = s + 1;
                if (mp + 1 == md) {
                    fj = d;
                } else {
                    int bc = u++;                        // clone of d, m = mp+1
                    S[bc] = (recd & ~((ull)IDA << M_SH)) | ((ull)(mp + 1) << M_SH);
                    S[d]  = (recd & ~((ull)IDA << F_SH)) | ((ull)bc << F_SH);
                    S[o]  = (rec  & ~((ull)IDA << ks))   | ((ull)bc << ks);
                    fj = bc;
                    // redirect pre-loop: walk while image == d (expected ~0-1)
                    for (; t < L; t++) {
                        int ot = OC[t];
                        ull rt = S[ot];
                        if ((int)((rt >> ks) & IDA) != d) break;
                        S[ot] = (rt & ~((ull)IDA << ks)) | ((ull)bc << ks);
                    }
                }
                NC[0] = (unsigned short)j;
                NC[1] = (unsigned short)fj;
                Sr[(fj << 2) | 3] = rv;
                nidx = 2;
                int prev = fj;
                // Branch-free rebuild + r-propagation. Dup Sr stores are
                // idempotent (same rv); dup NC slot overwritten next iter.
#pragma unroll 4
                for (; t < L; t++) {
                    int ot = OC[t];
                    ull rt = S[ot];
                    int tgt = (int)((rt >> ks) & IDA);
                    Sr[(tgt << 2) | 3] = rv;
                    NC[nidx] = (unsigned short)tgt;
                    nidx += (tgt != prev);
                    prev = tgt;
                }
                NC[nidx++] = 0;                          // root terminal
            }
            { unsigned short* tmp = OC; OC = NC; NC = tmp; }
            L = nidx;
            if (L > CAP - 2) degraded = true;
        } else {
            // ---- degraded fallback: reference-style dependent walks ----
            int p2 = g;
            for (;;) {
                if (p2 < 0) { fj = 0; break; }
                ull t = S[p2];
                int tk = (int)((t >> ks) & IDA);
                if (tk == IDA) {
                    S[p2] = (t & ~((ull)IDA << ks)) | ((ull)j << ks);
                    int f = (int)((t >> F_SH) & IDA);
                    p2 = (f == IDA) ? -1 : f;
                } else {
                    int d = tk;
                    ull recd = S[d];
                    int md = (int)((recd >> M_SH) & IDA);
                    int mp = (int)((t >> M_SH) & IDA);
                    if (mp + 1 == md) {
                        fj = d;
                    } else {
                        int bc = u++;
                        S[bc] = (recd & ~((ull)IDA << M_SH)) | ((ull)(mp + 1) << M_SH);
                        S[d]  = (recd & ~((ull)IDA << F_SH)) | ((ull)bc << F_SH);
                        fj = bc;
                        for (;;) {
                            ull t2 = S[p2];
                            if (((t2 >> ks) & IDA) != (ull)d) break;
                            S[p2] = (t2 & ~((ull)IDA << ks)) | ((ull)bc << ks);
                            int f = (int)((t2 >> F_SH) & IDA);
                            if (f == IDA) break;
                            p2 = f;
                        }
                    }
                    break;
                }
            }
            int vst = fj;
            while (vst != 0) {
                ull rc = S[vst];
                Sr[(vst << 2) | 3] = rv;
                int f = (int)((rc >> F_SH) & IDA);
                if (f == IDA) break;
                vst = f;
            }
        }

        // new state j: tr absent, f=fj, m=i+1, r+1=i+1
        S[j] = (ull)IDA | ((ull)IDA << 12)
             | ((ull)fj << F_SH)
             | ((ull)(i + 1) << M_SH)
             | ((ull)(i + 1) << R_SH);
        g = j;
    }
}

extern "C" void kernel_launch(void* const* d_in, const int* in_sizes, int n_in,
                              void* d_out, int out_size) {
    const float* q = (const float*)d_in[0];
    const float* k = (const float*)d_in[1];
    const float* v = (const float*)d_in[2];
    const float* e = (const float*)d_in[3];
    float* out = (float*)d_out;

    dim3 pg(WPB, BB);
    samx_pack_kernel<<<pg, CC>>>(q, k, v);

    size_t smem = (size_t)RPB * STATES * sizeof(ull)
                + (size_t)RPB * WPB * sizeof(uint32_t)
                + (size_t)RPB * 2 * CAP * sizeof(unsigned short);  // 232288
    cudaFuncSetAttribute(samx_sam_kernel,
                         cudaFuncAttributeMaxDynamicSharedMemorySize, (int)smem);
    int blocks = (NROWS + RPB - 1) / RPB;                 // 147
    samx_sam_kernel<<<blocks, 32 * RPB, smem>>>(e, out);
}

// round 7
// speedup vs baseline: 1.8140x; 1.3366x over previous
#include <cuda_runtime.h>
#include <stdint.h>

// samx_qkv_1bit: suffix-automaton retrieval, 1024 independent serial rows.
// R7: WARP-COOPERATIVE key side. The explicit suffix chain (length L <= ~28
//     for this data) is processed by all 32 lanes: parallel record loads,
//     ballot-derived split point, parallel plants/redirects, shuffle-based
//     dedup + compaction, parallel idempotent r-stores. Query stays serial
//     on lane 0. Serial-walk fallback if L ever exceeds 32 (correct for any
//     input; never triggers on random data).
// smem/block: 229376 (records) + 1792 (vpk) + 1120 (chains) = 232288.

#define BB 4
#define TT 2048
#define CC 256
#define NROWS (BB*CC)          // 1024
#define WPB (TT/32)            // 64 packed words per row
#define STATES 4096            // SAM has <= 2n-1 = 4095 states
#define RPB 7                  // rows (warps) per block
#define CAP 40                 // NC capacity (writes reach at most L+2 <= 34)

typedef unsigned long long ull;
#define IDA 0xFFF              // 12-bit absent / -1 marker
#define F_SH 24
#define M_SH 36
#define R_SH 48
#define FULLM 0xFFFFFFFFu

__device__ uint32_t g_qpack[NROWS*WPB];
__device__ uint32_t g_kpack[NROWS*WPB];
__device__ uint32_t g_vpack[NROWS*WPB];

// ---------------------------------------------------------------------------
__global__ void samx_pack_kernel(const float* __restrict__ q,
                                 const float* __restrict__ k,
                                 const float* __restrict__ v) {
    int c  = threadIdx.x;
    int wi = blockIdx.x;
    int b  = blockIdx.y;
    int row = b * CC + c;
    size_t base = ((size_t)b * TT + (size_t)wi * 32) * CC + c;
    uint32_t qw = 0, kw = 0, vw = 0;
#pragma unroll
    for (int s = 0; s < 32; s++) {
        if (q[base + (size_t)s * CC] > 0.f) qw |= 1u << s;
        if (k[base + (size_t)s * CC] > 0.f) kw |= 1u << s;
        if (v[base + (size_t)s * CC] > 0.f) vw |= 1u << s;
    }
    g_qpack[row * WPB + wi] = qw;
    g_kpack[row * WPB + wi] = kw;
    g_vpack[row * WPB + wi] = vw;
}

// ---------------------------------------------------------------------------
extern "C" __global__ void __launch_bounds__(32*RPB, 1)
samx_sam_kernel(const float* __restrict__ e, float* __restrict__ out) {
    extern __shared__ ull smem[];
    int warp = threadIdx.x >> 5;
    int lane = threadIdx.x & 31;
    int row  = blockIdx.x * RPB + warp;

    ull* S = smem + (size_t)warp * STATES;
    unsigned short* Sr = (unsigned short*)S;              // r+1 halfword = idx 4n+3
    uint32_t* vpk_s = (uint32_t*)(smem + (size_t)RPB * STATES) + warp * WPB;
    unsigned short* CH = (unsigned short*)((char*)smem
                        + (size_t)RPB * STATES * sizeof(ull)
                        + (size_t)RPB * WPB * sizeof(uint32_t))
                        + warp * 2 * CAP;

    if (row < NROWS) {
        vpk_s[lane]      = g_vpack[row * WPB + lane];
        vpk_s[lane + 32] = g_vpack[row * WPB + lane + 32];
    }
    __syncwarp();
    if (row >= NROWS) return;

    const uint32_t* qpk = g_qpack + row * WPB;
    const uint32_t* kpk = g_kpack + row * WPB;

    int b = row >> 8;
    int c = row & (CC - 1);
    float ev = e[c];
    float* op = out + (size_t)b * TT * CC + c;

    if (lane == 0) {
        // root: tr absent, f=-1, m=0
        S[0] = (ull)IDA | ((ull)IDA << 12) | ((ull)IDA << F_SH);
        CH[0] = 0;
    }
    __syncwarp();

    unsigned short* OC = CH;
    unsigned short* NC = CH + CAP;
    int L = 1;
    bool degraded = false;

    int g = 0, u = 1, w = 0, h = 0;
    uint32_t qw = 0, kw = 0;

    for (int i = 0; i < TT; i++) {
        if ((i & 31) == 0) {
            uint32_t tq = 0, tk2 = 0;
            if (lane == 0) { int wi = i >> 5; tq = qpk[wi]; tk2 = kpk[wi]; }
            qw = __shfl_sync(FULLM, tq, 0);
            kw = __shfl_sync(FULLM, tk2, 0);
        }
        int qs = ((qw >> (i & 31)) & 1) ? 12 : 0;
        int ks = ((kw >> (i & 31)) & 1) ? 12 : 0;

        // ---- query: lane 0 serial (short dependent walk) ----
        if (lane == 0) {
            int p = w, x = h;
            for (;;) {
                if (p < 0) { p = 0; x = 0; break; }
                ull rec = S[p];
                int tq = (int)((rec >> qs) & IDA);
                if (tq != IDA) { p = tq; x += 1; break; }
                int mp = (int)((rec >> M_SH) & IDA);
                if (x > mp) x = mp;
                int f = (int)((rec >> F_SH) & IDA);
                p = (f == IDA) ? -1 : f;
            }
            int y = 0;
            if (x > 0) {
                ull recv = S[p];
                for (;;) {
                    int f = (int)((recv >> F_SH) & IDA);
                    if (f == IDA) break;
                    ull recf = S[f];
                    if ((int)((recf >> M_SH) & IDA) >= x) recv = recf;
                    else break;
                }
                int idx = (int)(recv >> R_SH);          // r+1
                y = (int)((vpk_s[idx >> 5] >> (idx & 31)) & 1u);
            }
            op[(size_t)i * CC] = y ? ev : -ev;
            w = p; h = x;
        }
        __syncwarp();   // key writes must not start before query reads finish

        int j = u;                                       // new node id (uniform)
        unsigned short rv = (unsigned short)(i + 1);

        if (!degraded) {
            // --- phase 1: parallel chain-record loads + split-point ballot ---
            int t = lane;
            bool validt = (t < L);
            int ot = validt ? (int)OC[t] : 0;
            ull rec = S[ot];
            int tkt = (int)((rec >> ks) & IDA);
            int mpt = (int)((rec >> M_SH) & IDA);
            unsigned present = __ballot_sync(FULLM, validt && (tkt != IDA));
            int s = present ? (__ffs(present) - 1) : L;

            // --- phase 2: parallel plants tk=j for t<s ---
            if (validt && t < s)
                S[ot] = (rec & ~((ull)IDA << ks)) | ((ull)j << ks);
            __syncwarp();   // plants visible before S[d] reload (d may be on chain)

            int Lnext;
            if (present) {
                int d  = __shfl_sync(FULLM, tkt, s);
                int mp = __shfl_sync(FULLM, mpt, s);
                ull recd = S[d];                         // broadcast load, post-plant
                int md = (int)((recd >> M_SH) & IDA);
                bool clone = (mp + 1 != md);             // uniform
                int fj, tgt = tkt;
                if (clone) {
                    int bc = u + 1;
                    fj = bc;
                    // contiguous redirect run starting at s+1
                    unsigned nd = ~__ballot_sync(FULLM, validt && (tkt == d));
                    unsigned hi = (s >= 31) ? 0u : (nd & ~((2u << s) - 1u));
                    int end = hi ? (__ffs(hi) - 1) : 32;
                    bool inrun = (t > s) && (t < end) && validt;
                    if (t == s)
                        S[ot] = (rec & ~((ull)IDA << ks)) | ((ull)bc << ks);
                    if (lane == 0) {
                        // clone record: m = mp+1, r = rv (on new chain)
                        S[bc] = (recd & ~(((ull)IDA << M_SH) | (0xFFFFull << R_SH)))
                              | ((ull)(mp + 1) << M_SH) | ((ull)rv << R_SH);
                        S[d]  = (recd & ~((ull)IDA << F_SH)) | ((ull)bc << F_SH);
                    }
                    if (inrun)
                        S[ot] = (rec & ~((ull)IDA << ks)) | ((ull)bc << ks);
                    if (inrun) tgt = bc;
                    u += 2;
                } else {
                    fj = d;
                    if (lane == 0) Sr[(d << 2) | 3] = rv;
                    u += 1;
                }
                __syncwarp();   // clone/redirect full-record writes before r-stores

                // --- phase 4: NC dedup-compaction + parallel r-propagation ---
                if (t == s) tgt = fj;
                int prevtgt = __shfl_up_sync(FULLM, tgt, 1);
                bool vrange = validt && (t > s);
                bool keep = vrange && (tgt != prevtgt);
                unsigned keepm = __ballot_sync(FULLM, keep);
                if (vrange) Sr[(tgt << 2) | 3] = rv;     // dups idempotent
                int pos = 2 + __popc(keepm & ((1u << t) - 1u));
                if (keep) NC[pos] = (unsigned short)tgt;
                int nk = __popc(keepm);
                if (lane == 0) {
                    NC[0] = (unsigned short)j;
                    NC[1] = (unsigned short)fj;
                    NC[2 + nk] = 0;                      // root terminal
                    S[j] = (ull)IDA | ((ull)IDA << 12)
                         | ((ull)fj << F_SH)
                         | ((ull)(i + 1) << M_SH)
                         | ((ull)(i + 1) << R_SH);
                }
                Lnext = nk + 3;
            } else {
                // symbol never seen anywhere on chain: fj = 0
                if (lane == 0) {
                    NC[0] = (unsigned short)j;
                    NC[1] = 0;
                    S[j] = (ull)IDA | ((ull)IDA << 12)
                         | ((ull)0 << F_SH)
                         | ((ull)(i + 1) << M_SH)
                         | ((ull)(i + 1) << R_SH);
                }
                u += 1;
                Lnext = 2;
            }
            { unsigned short* tmp = OC; OC = NC; NC = tmp; }
            L = Lnext;
            g = j;
            if (L > 32) degraded = true;                 // NC held <= L+2 <= 34 < CAP
        } else {
            // ---- serial fallback: reference-style dependent walks ----
            if (lane == 0) {
                int fj;
                int p2 = g;
                for (;;) {
                    if (p2 < 0) { fj = 0; break; }
                    ull t2r = S[p2];
                    int tk = (int)((t2r >> ks) & IDA);
                    if (tk == IDA) {
                        S[p2] = (t2r & ~((ull)IDA << ks)) | ((ull)j << ks);
                        int f = (int)((t2r >> F_SH) & IDA);
                        p2 = (f == IDA) ? -1 : f;
                    } else {
                        int d = tk;
                        ull recd = S[d];
                        int md = (int)((recd >> M_SH) & IDA);
                        int mp = (int)((t2r >> M_SH) & IDA);
                        if (mp + 1 == md) {
                            fj = d;
                        } else {
                            int bc = u + 1;
                            S[bc] = (recd & ~((ull)IDA << M_SH)) | ((ull)(mp + 1) << M_SH);
                            S[d]  = (recd & ~((ull)IDA << F_SH)) | ((ull)bc << F_SH);
                            fj = bc;
                            u += 1;
                            for (;;) {
                                ull t3 = S[p2];
                                if (((t3 >> ks) & IDA) != (ull)d) break;
                                S[p2] = (t3 & ~((ull)IDA << ks)) | ((ull)bc << ks);
                                int f = (int)((t3 >> F_SH) & IDA);
                                if (f == IDA) break;
                                p2 = f;
                            }
                        }
                        break;
                    }
                }
                int vst = fj;
                while (vst != 0) {
                    ull rc = S[vst];
                    Sr[(vst << 2) | 3] = rv;
                    int f = (int)((rc >> F_SH) & IDA);
                    if (f == IDA) break;
                    vst = f;
                }
                S[j] = (ull)IDA | ((ull)IDA << 12)
                     | ((ull)fj << F_SH)
                     | ((ull)(i + 1) << M_SH)
                     | ((ull)(i + 1) << R_SH);
                g = j;
                u += 1;
            }
        }
        __syncwarp();   // all key writes visible to next step's query
    }
}

extern "C" void kernel_launch(void* const* d_in, const int* in_sizes, int n_in,
                              void* d_out, int out_size) {
    const float* q = (const float*)d_in[0];
    const float* k = (const float*)d_in[1];
    const float* v = (const float*)d_in[2];
    const float* e = (const float*)d_in[3];
    float* out = (float*)d_out;

    dim3 pg(WPB, BB);
    samx_pack_kernel<<<pg, CC>>>(q, k, v);

    size_t smem = (size_t)RPB * STATES * sizeof(ull)
                + (size_t)RPB * WPB * sizeof(uint32_t)
                + (size_t)RPB * 2 * CAP * sizeof(unsigned short);  // 232288
    cudaFuncSetAttribute(samx_sam_kernel,
                         cudaFuncAttributeMaxDynamicSharedMemorySize, (int)smem);
    int blocks = (NROWS + RPB - 1) / RPB;                 // 147
    samx_sam_kernel<<<blocks, 32 * RPB, smem>>>(e, out);
}

// round 9
// speedup vs baseline: 1.8778x; 1.0352x over previous
#include <cuda_runtime.h>
#include <stdint.h>

// samx_qkv_1bit: suffix-automaton retrieval, 1024 independent serial rows.
// R9 = R8 (register-resident suffix chain, warp-cooperative key side) with
//      three carry-coherence fixes:
//        1) fj's carried record derived from broadcast recd (was shfl of S[0])
//        2) tgt uses bc only when clone (was corrupting non-clone dedup)
//        3) root record carried via updrec (plant/redirect applied)
//      smem S[] remains the source of truth for the serial query walk.
// smem/block: 229376 (records) + 1792 (vpk) = 231168.

#define BB 4
#define TT 2048
#define CC 256
#define NROWS (BB*CC)          // 1024
#define WPB (TT/32)            // 64 packed words per row
#define STATES 4096            // SAM has <= 2n-1 = 4095 states
#define RPB 7                  // rows (warps) per block

typedef unsigned long long ull;
#define IDA 0xFFF              // 12-bit absent / -1 marker
#define F_SH 24
#define M_SH 36
#define R_SH 48
#define FULLM 0xFFFFFFFFu
#define RMASK (0xFFFFull << R_SH)
#define MMASK ((ull)IDA << M_SH)
#define FMASK ((ull)IDA << F_SH)

__device__ uint32_t g_qpack[NROWS*WPB];
__device__ uint32_t g_kpack[NROWS*WPB];
__device__ uint32_t g_vpack[NROWS*WPB];

// ---------------------------------------------------------------------------
__global__ void samx_pack_kernel(const float* __restrict__ q,
                                 const float* __restrict__ k,
                                 const float* __restrict__ v) {
    int c  = threadIdx.x;
    int wi = blockIdx.x;
    int b  = blockIdx.y;
    int row = b * CC + c;
    size_t base = ((size_t)b * TT + (size_t)wi * 32) * CC + c;
    uint32_t qw = 0, kw = 0, vw = 0;
#pragma unroll
    for (int s = 0; s < 32; s++) {
        if (q[base + (size_t)s * CC] > 0.f) qw |= 1u << s;
        if (k[base + (size_t)s * CC] > 0.f) kw |= 1u << s;
        if (v[base + (size_t)s * CC] > 0.f) vw |= 1u << s;
    }
    g_qpack[row * WPB + wi] = qw;
    g_kpack[row * WPB + wi] = kw;
    g_vpack[row * WPB + wi] = vw;
}

// ---------------------------------------------------------------------------
extern "C" __global__ void __launch_bounds__(32*RPB, 1)
samx_sam_kernel(const float* __restrict__ e, float* __restrict__ out) {
    extern __shared__ ull smem[];
    int warp = threadIdx.x >> 5;
    int lane = threadIdx.x & 31;
    int row  = blockIdx.x * RPB + warp;

    ull* S = smem + (size_t)warp * STATES;
    unsigned short* Sr = (unsigned short*)S;              // r+1 halfword = idx 4n+3
    uint32_t* vpk_s = (uint32_t*)(smem + (size_t)RPB * STATES) + warp * WPB;

    if (row < NROWS) {
        vpk_s[lane]      = g_vpack[row * WPB + lane];
        vpk_s[lane + 32] = g_vpack[row * WPB + lane + 32];
    }
    __syncwarp();
    if (row >= NROWS) return;

    const uint32_t* qpk = g_qpack + row * WPB;
    const uint32_t* kpk = g_kpack + row * WPB;

    int b = row >> 8;
    int c = row & (CC - 1);
    float ev = e[c];
    float* op = out + (size_t)b * TT * CC + c;

    // root record: tr absent, f=-1, m=0, r+1=0
    ull rootrec = (ull)IDA | ((ull)IDA << 12) | ((ull)IDA << F_SH);
    if (lane == 0) S[0] = rootrec;
    __syncwarp();

    // register-resident chain: lane t holds node t's (id, record); valid t<L
    ull myrec = rootrec;
    int myid = 0;
    int L = 1;
    bool degraded = false;

    int g = 0, u = 1, w = 0, h = 0;
    uint32_t qw = 0, kw = 0;

    for (int i = 0; i < TT; i++) {
        if ((i & 31) == 0) {
            uint32_t tq = 0, tk2 = 0;
            if (lane == 0) { int wi = i >> 5; tq = qpk[wi]; tk2 = kpk[wi]; }
            qw = __shfl_sync(FULLM, tq, 0);
            kw = __shfl_sync(FULLM, tk2, 0);
        }
        int qs = ((qw >> (i & 31)) & 1) ? 12 : 0;
        int ks = ((kw >> (i & 31)) & 1) ? 12 : 0;

        // ---- query: lane 0 serial (reads S only) ----
        if (lane == 0) {
            int p = w, x = h;
            for (;;) {
                if (p < 0) { p = 0; x = 0; break; }
                ull rec = S[p];
                int tq = (int)((rec >> qs) & IDA);
                if (tq != IDA) { p = tq; x += 1; break; }
                int mp = (int)((rec >> M_SH) & IDA);
                if (x > mp) x = mp;
                int f = (int)((rec >> F_SH) & IDA);
                p = (f == IDA) ? -1 : f;
            }
            int y = 0;
            if (x > 0) {
                ull recv = S[p];
                for (;;) {
                    int f = (int)((recv >> F_SH) & IDA);
                    if (f == IDA) break;
                    ull recf = S[f];
                    if ((int)((recf >> M_SH) & IDA) >= x) recv = recf;
                    else break;
                }
                int idx = (int)(recv >> R_SH);          // r+1
                y = (int)((vpk_s[idx >> 5] >> (idx & 31)) & 1u);
            }
            op[(size_t)i * CC] = y ? ev : -ev;
            w = p; h = x;
        }
        __syncwarp();   // query reads done before key writes

        int j = u;
        unsigned short rv = (unsigned short)(i + 1);

        if (!degraded) {
            int t = lane;
            bool validt = (t < L);
            int tkt = validt ? (int)((myrec >> ks) & IDA) : IDA;
            int mpt = (int)((myrec >> M_SH) & IDA);
            unsigned present = __ballot_sync(FULLM, tkt != IDA);
            int s = present ? (__ffs(present) - 1) : L;

            // plants (t < s implies validt since tkt==IDA only possible... invalid lanes have tkt=IDA but t>=L>=s)
            ull planted = (myrec & ~((ull)IDA << ks)) | ((ull)j << ks);
            if (t < s) S[myid] = planted;
            int d = __shfl_sync(FULLM, tkt, s & 31);
            __syncwarp();   // plants visible before any S reads below

            ull jrec = (ull)IDA | ((ull)IDA << 12)
                     | ((ull)(i + 1) << M_SH) | ((ull)(i + 1) << R_SH);
            ull nrec; int nid; int Lnext;

            if (present) {
                ull recd = S[d];                        // broadcast, post-plant
                int mp = __shfl_sync(FULLM, mpt, s);
                int md = (int)((recd >> M_SH) & IDA);
                bool clone = (mp + 1 != md);            // uniform
                int bc = j + 1;
                int fj = clone ? bc : d;
                jrec |= ((ull)fj << F_SH);
                bool hitd = validt && (tkt == d);       // t==s or redirect run

                // updated register record for this step's mutations
                ull redirected = (myrec & ~((ull)IDA << ks)) | ((ull)bc << ks);
                ull updrec = (t < s) ? planted
                           : ((clone && hitd) ? redirected : myrec);

                // fj's record, derived from broadcast recd (fix #1)
                ull fjrec = clone
                    ? ((recd & ~(MMASK | RMASK))
                        | ((ull)(mp + 1) << M_SH) | ((ull)rv << R_SH))
                    : ((recd & ~RMASK) | ((ull)rv << R_SH));

                if (clone) {
                    if (t == s) {
                        S[myid] = redirected;
                        S[d]  = (recd & ~FMASK) | ((ull)bc << F_SH);
                        S[bc] = fjrec;
                    } else if (hitd) {
                        S[myid] = redirected;           // redirect run
                    }
                    __syncwarp();   // clone/redirect stores before image loads
                } else {
                    if (t == s) Sr[(d << 2) | 3] = rv;
                }

                // image loads (become next chain records)
                bool inrun = (t > s) && hitd;
                bool vimg = validt && (t > s) && !inrun;
                ull imgrec = S[vimg ? tkt : 0];
                ull imgrecP = (imgrec & ~RMASK) | ((ull)rv << R_SH);

                int tgt = (clone && inrun) ? bc : tkt;  // fix #2
                if (t == s) tgt = fj;
                // r-propagation for images (dups idempotent)
                if (validt && t > s) Sr[(tgt << 2) | 3] = rv;

                int prevtgt = __shfl_up_sync(FULLM, tgt, 1);
                bool keep = validt && (t > s) && (tgt != prevtgt);
                unsigned keepm = __ballot_sync(FULLM, keep);
                int nk = __popc(keepm);
                Lnext = nk + 3;

                // source lane for dst positions 2..nk+1: (t-1)-th set bit (1-idx)
                int srcsel;
                {
                    int o = t - 1;
                    unsigned m2 = keepm; int sp = 0; int cth;
                    cth = __popc(m2 & 0xFFFFu); if (o > cth) { sp += 16; o -= cth; m2 >>= 16; }
                    cth = __popc(m2 & 0xFFu);   if (o > cth) { sp += 8;  o -= cth; m2 >>= 8; }
                    cth = __popc(m2 & 0xFu);    if (o > cth) { sp += 4;  o -= cth; m2 >>= 4; }
                    cth = __popc(m2 & 0x3u);    if (o > cth) { sp += 2;  o -= cth; m2 >>= 2; }
                    cth = (int)(m2 & 1u);       if (o > cth) { sp += 1; }
                    srcsel = sp;
                }
                ull recA = __shfl_sync(FULLM, imgrecP, srcsel);
                int idA  = __shfl_sync(FULLM, tgt, srcsel);
                ull recRoot = __shfl_sync(FULLM, updrec, L - 1);  // fix #3

                if (t == 0)          { nrec = jrec; nid = j; S[j] = jrec; }
                else if (t == 1)     { nrec = fjrec; nid = fj; }
                else if (t < 2 + nk) { nrec = recA; nid = idA; }
                else                 { nrec = recRoot; nid = 0; }  // terminal root

                u += clone ? 2 : 1;
            } else {
                // symbol unseen on whole chain (all planted, incl. root): fj=0
                ull recRootP = __shfl_sync(FULLM, planted, L - 1);
                if (t == 0) { nrec = jrec; nid = j; S[j] = jrec; }
                else        { nrec = recRootP; nid = 0; }
                Lnext = 2;
                u += 1;
            }
            myrec = nrec; myid = nid;
            L = Lnext; g = j;
            if (L > 32) degraded = true;   // S fully coherent; fallback takes over
        } else {
            // ---- serial fallback: reference-style dependent walks ----
            if (lane == 0) {
                int fj;
                int p2 = g;
                for (;;) {
                    if (p2 < 0) { fj = 0; break; }
                    ull t2r = S[p2];
                    int tk = (int)((t2r >> ks) & IDA);
                    if (tk == IDA) {
                        S[p2] = (t2r & ~((ull)IDA << ks)) | ((ull)j << ks);
                        int f = (int)((t2r >> F_SH) & IDA);
                        p2 = (f == IDA) ? -1 : f;
                    } else {
                        int d = tk;
                        ull recd = S[d];
                        int md = (int)((recd >> M_SH) & IDA);
                        int mp = (int)((t2r >> M_SH) & IDA);
                        if (mp + 1 == md) {
                            fj = d;
                        } else {
                            int bc = j + 1;
                            S[bc] = (recd & ~MMASK) | ((ull)(mp + 1) << M_SH);
                            S[d]  = (recd & ~FMASK) | ((ull)bc << F_SH);
                            fj = bc;
                            u += 1;
                            for (;;) {
                                ull t3 = S[p2];
                                if (((t3 >> ks) & IDA) != (ull)d) break;
                                S[p2] = (t3 & ~((ull)IDA << ks)) | ((ull)bc << ks);
                                int f = (int)((t3 >> F_SH) & IDA);
                                if (f == IDA) break;
                                p2 = f;
                            }
                        }
                        break;
                    }
                }
                int vst = fj;
                while (vst != 0) {
                    ull rc = S[vst];
                    Sr[(vst << 2) | 3] = rv;
                    int f = (int)((rc >> F_SH) & IDA);
                    if (f == IDA) break;
                    vst = f;
                }
                S[j] = (ull)IDA | ((ull)IDA << 12)
                     | ((ull)fj << F_SH)
                     | ((ull)(i + 1) << M_SH)
                     | ((ull)(i + 1) << R_SH);
                g = j;
                u += 1;
            }
            g = __shfl_sync(FULLM, g, 0);
            u = __shfl_sync(FULLM, u, 0);
        }
        __syncwarp();   // key writes visible to next step's query
    }
}

extern "C" void kernel_launch(void* const* d_in, const int* in_sizes, int n_in,
                              void* d_out, int out_size) {
    const float* q = (const float*)d_in[0];
    const float* k = (const float*)d_in[1];
    const float* v = (const float*)d_in[2];
    const float* e = (const float*)d_in[3];
    float* out = (float*)d_out;

    dim3 pg(WPB, BB);
    samx_pack_kernel<<<pg, CC>>>(q, k, v);

    size_t smem = (size_t)RPB * STATES * sizeof(ull)
                + (size_t)RPB * WPB * sizeof(uint32_t);   // 231168
    cudaFuncSetAttribute(samx_sam_kernel,
                         cudaFuncAttributeMaxDynamicSharedMemorySize, (int)smem);
    int blocks = (NROWS + RPB - 1) / RPB;                 // 147
    samx_sam_kernel<<<blocks, 32 * RPB, smem>>>(e, out);
}